// round 7
// baseline (speedup 1.0000x reference)
#include <cuda_runtime.h>

#define N_MAX     1048576
#define SEGS      (64 * 4096)   // 262144 segments
#define GRID_DIM  64
#define NUM_CELLS 4096
#define SCAN_BLOCKS 256
#define CPB       32            // cells per gather block
#define STAGE_MAX 512           // staged pids per gather block
#define IDX_BITS  18            // SEGS = 2^18

// ---- scratch (static device globals; zero-initialized at module load) ----
__device__ int g_idx[N_MAX];           // packed: cell idx | rank<<18
__device__ int g_pids[N_MAX];          // point ids sorted by cell
__device__ int g_counts[SEGS];         // points per cell (re-zeroed by k_scan)
__device__ int g_offsets[SEGS + 1];    // exclusive prefix + sentinel
__device__ int g_blocksums[SCAN_BLOCKS];
__device__ int g_prefix[SCAN_BLOCKS];  // exclusive scan of block totals
__device__ int g_done;                 // arrival counter (reset by k_gather)
__device__ int g_flag;                 // publish flag   (reset by k_gather)

// ---------------------------------------------------------------
// pos/batch are int32 (JAX x64 disabled => int64 request materializes int32).
// atomicAdd's return value = this point's rank within its cell -> packed into
// g_idx so k_scatter needs no atomics.
__global__ void k_hist(const int2* __restrict__ pos,
                       const int* __restrict__ batch, int n) {
    int i = blockIdx.x * blockDim.x + threadIdx.x;
    if (i >= n) return;
    int2 p = pos[i];
    int idx = batch[i] * NUM_CELLS
            + (p.x >> 2) * GRID_DIM
            + (p.y >> 2);
    int rank = atomicAdd(&g_counts[idx], 1);
    g_idx[i] = idx | (rank << IDX_BITS);
}

// Single-pass scan, single-hop sync: all 256 blocks co-resident (1024 thr ->
// >=2 blocks/SM on 148 SMs). Each block scans locally and posts its total;
// the LAST block to arrive scans the 256 totals and publishes; all add base.
__global__ void k_scan(int n) {
    int bid  = blockIdx.x;
    int i    = bid * 1024 + threadIdx.x;
    int lane = threadIdx.x & 31;
    int wid  = threadIdx.x >> 5;

    int v = g_counts[i];
    g_counts[i] = 0;                       // consumed; reset for next replay

    int incl = v;
    #pragma unroll
    for (int d = 1; d < 32; d <<= 1) {
        int u = __shfl_up_sync(0xffffffffu, incl, d);
        if (lane >= d) incl += u;
    }
    __shared__ int ws[32];
    __shared__ int wexcl[32];
    __shared__ int s_last;
    __shared__ int s_base;
    if (lane == 31) ws[wid] = incl;
    __syncthreads();
    if (wid == 0) {
        int w  = ws[lane];
        int wi = w;
        #pragma unroll
        for (int d = 1; d < 32; d <<= 1) {
            int u = __shfl_up_sync(0xffffffffu, wi, d);
            if (lane >= d) wi += u;
        }
        wexcl[lane] = wi - w;
        if (lane == 31) {
            g_blocksums[bid] = wi;         // block total
            __threadfence();
            int t = atomicAdd(&g_done, 1);
            s_last = (t == SCAN_BLOCKS - 1);
        }
    }
    __syncthreads();

    if (s_last) {                          // block-uniform branch
        __shared__ int ws2[8];
        int t = threadIdx.x;
        int bv = 0, bi = 0;
        if (t < SCAN_BLOCKS) {
            bv = g_blocksums[t];
            bi = bv;
            #pragma unroll
            for (int d = 1; d < 32; d <<= 1) {
                int u = __shfl_up_sync(0xffffffffu, bi, d);
                if ((t & 31) >= d) bi += u;
            }
            if ((t & 31) == 31) ws2[t >> 5] = bi;
        }
        __syncthreads();
        if (t < SCAN_BLOCKS) {
            int add = 0;
            #pragma unroll
            for (int wq = 0; wq < 8; wq++)
                if (wq < (t >> 5)) add += ws2[wq];
            g_prefix[t] = bi - bv + add;   // exclusive base for block t
        }
        __syncthreads();
        if (t == 0) {
            __threadfence();
            atomicExch(&g_flag, 1);        // publish
        }
    }

    if (threadIdx.x == 0) {                // single-hop wait
        while (atomicAdd(&g_flag, 0) == 0) { __nanosleep(100); }
        __threadfence();
        s_base = g_prefix[bid];
    }
    __syncthreads();

    g_offsets[i] = incl - v + wexcl[wid] + s_base;
    if (bid == SCAN_BLOCKS - 1 && threadIdx.x == 1023)
        g_offsets[SEGS] = n;               // sentinel for count derivation
}

// atomic-free scatter: position = offsets[idx] + rank (offsets L2-hot, 1MB)
__global__ void k_scatter(int n) {
    int i = blockIdx.x * blockDim.x + threadIdx.x;
    if (i >= n) return;
    int packed = g_idx[i];
    int idx  = packed & (SEGS - 1);
    int rank = ((unsigned)packed) >> IDX_BITS;
    g_pids[g_offsets[idx] + rank] = i;
}

// Gather: block = 32 contiguous cells; pids staged in smem (contiguous range).
// Each warp accumulates its 4 cells CONCURRENTLY (one j-loop over the max
// count, per-cell predicated loads) -> up to 8 independent 256B row loads in
// flight per warp instead of ~2.
__global__ void k_gather(const float4* __restrict__ x4, float4* __restrict__ out4) {
    if (blockIdx.x == 0 && threadIdx.x == 0) { g_done = 0; g_flag = 0; }

    __shared__ int s_off[CPB + 1];
    __shared__ int s_pid[STAGE_MAX];

    int tid   = threadIdx.x;
    int cbase = blockIdx.x * CPB;

    if (tid < CPB + 1)
        s_off[tid] = g_offsets[cbase + tid];
    __syncthreads();

    int base0 = s_off[0];
    int total = s_off[CPB] - base0;
    bool all_staged = (total <= STAGE_MAX);
    int stage = all_staged ? total : 0;      // partial staging not worth the branchiness
    for (int i = tid; i < stage; i += 256)
        s_pid[i] = g_pids[base0 + i];
    __syncthreads();

    int warp = tid >> 5;
    int lane = tid & 31;
    int g    = lane >> 4;       // point-pair group (0/1)
    int s    = lane & 15;       // float4 column within 64-ch row
    int c0   = warp * 4;        // first of this warp's 4 cells

    const float ninf = __int_as_float(0xff800000);

    int cnts[4], lss[4];
    int jmax = 0;
    #pragma unroll
    for (int ci = 0; ci < 4; ci++) {
        int a = s_off[c0 + ci], b = s_off[c0 + ci + 1];
        cnts[ci] = b - a;
        lss[ci]  = a - base0;
        jmax = cnts[ci] > jmax ? cnts[ci] : jmax;
    }

    float4 acc[4];
    #pragma unroll
    for (int ci = 0; ci < 4; ci++)
        acc[ci] = make_float4(ninf, ninf, ninf, ninf);

    for (int j = 0; j < jmax; j += 2) {
        #pragma unroll
        for (int ci = 0; ci < 4; ci++) {
            if (j < cnts[ci]) {
                int jj = j + g; if (jj >= cnts[ci]) jj = cnts[ci] - 1; // odd tail dup
                int pid = all_staged ? s_pid[lss[ci] + jj]
                                     : g_pids[base0 + lss[ci] + jj];
                float4 v = x4[pid * 16 + s];       // 256B row, 2 points/iter
                acc[ci].x = fmaxf(acc[ci].x, v.x);
                acc[ci].y = fmaxf(acc[ci].y, v.y);
                acc[ci].z = fmaxf(acc[ci].z, v.z);
                acc[ci].w = fmaxf(acc[ci].w, v.w);
            }
        }
    }

    #pragma unroll
    for (int ci = 0; ci < 4; ci++) {
        float4 a = acc[ci];
        a.x = fmaxf(a.x, __shfl_xor_sync(0xffffffffu, a.x, 16));
        a.y = fmaxf(a.y, __shfl_xor_sync(0xffffffffu, a.y, 16));
        a.z = fmaxf(a.z, __shfl_xor_sync(0xffffffffu, a.z, 16));
        a.w = fmaxf(a.w, __shfl_xor_sync(0xffffffffu, a.w, 16));
        if (cnts[ci] == 0) a = make_float4(0.f, 0.f, 0.f, 0.f);
        if (lane < 16) out4[(cbase + c0 + ci) * 16 + lane] = a;  // 256B STG.128
    }
}

// ---------------------------------------------------------------
extern "C" void kernel_launch(void* const* d_in, const int* in_sizes, int n_in,
                              void* d_out, int out_size) {
    const float* x     = (const float*)d_in[0];
    const int2*  pos   = (const int2*)d_in[1];
    const int*   batch = (const int*)d_in[2];
    float* out = (float*)d_out;
    int n = in_sizes[2];     // number of points

    k_hist   <<<(n + 255) / 256, 256>>>(pos, batch, n);
    k_scan   <<<SCAN_BLOCKS, 1024>>>(n);
    k_scatter<<<(n + 255) / 256, 256>>>(n);
    k_gather <<<SEGS / CPB, 256>>>((const float4*)x, (float4*)out);
}

// round 8
// speedup vs baseline: 1.1446x; 1.1446x over previous
#include <cuda_runtime.h>

#define N_MAX     1048576
#define SEGS      (64 * 4096)   // 262144 segments
#define GRID_DIM  64
#define NUM_CELLS 4096
#define SCAN_BLOCKS 256
#define CPB       32            // cells per gather block
#define STAGE_MAX 512           // staged pids per gather block
#define IDX_BITS  18            // SEGS = 2^18

// ---- scratch (static device globals; zero-initialized at module load) ----
__device__ int g_idx[N_MAX];           // packed: cell idx | rank<<18
__device__ int g_pids[N_MAX];          // point ids sorted by cell
__device__ int g_counts[SEGS];         // points per cell (re-zeroed by k_scan)
__device__ int g_offsets[SEGS + 1];    // exclusive prefix + sentinel
__device__ int g_blocksums[SCAN_BLOCKS];
__device__ int g_prefix[SCAN_BLOCKS];  // exclusive scan of block totals
__device__ int g_done;                 // arrival counter (reset by k_gather)
__device__ int g_flag;                 // publish flag   (reset by k_gather)

// ---------------------------------------------------------------
// pos/batch are int32 (JAX x64 disabled => int64 request materializes int32).
// atomicAdd's return value = this point's rank within its cell -> packed into
// g_idx so k_scatter needs no atomics.
__global__ void k_hist(const int2* __restrict__ pos,
                       const int* __restrict__ batch, int n) {
    int i = blockIdx.x * blockDim.x + threadIdx.x;
    if (i >= n) return;
    int2 p = pos[i];
    int idx = batch[i] * NUM_CELLS
            + (p.x >> 2) * GRID_DIM
            + (p.y >> 2);
    int rank = atomicAdd(&g_counts[idx], 1);
    g_idx[i] = idx | (rank << IDX_BITS);
}

// Single-pass scan, single-hop sync: all 256 blocks co-resident (1024 thr ->
// >=2 blocks/SM on 148 SMs). Each block scans locally and posts its total;
// the LAST block to arrive scans the 256 totals and publishes; all add base.
__global__ void k_scan(int n) {
    int bid  = blockIdx.x;
    int i    = bid * 1024 + threadIdx.x;
    int lane = threadIdx.x & 31;
    int wid  = threadIdx.x >> 5;

    int v = g_counts[i];
    g_counts[i] = 0;                       // consumed; reset for next replay

    int incl = v;
    #pragma unroll
    for (int d = 1; d < 32; d <<= 1) {
        int u = __shfl_up_sync(0xffffffffu, incl, d);
        if (lane >= d) incl += u;
    }
    __shared__ int ws[32];
    __shared__ int wexcl[32];
    __shared__ int s_last;
    __shared__ int s_base;
    if (lane == 31) ws[wid] = incl;
    __syncthreads();
    if (wid == 0) {
        int w  = ws[lane];
        int wi = w;
        #pragma unroll
        for (int d = 1; d < 32; d <<= 1) {
            int u = __shfl_up_sync(0xffffffffu, wi, d);
            if (lane >= d) wi += u;
        }
        wexcl[lane] = wi - w;
        if (lane == 31) {
            g_blocksums[bid] = wi;         // block total
            __threadfence();
            int t = atomicAdd(&g_done, 1);
            s_last = (t == SCAN_BLOCKS - 1);
        }
    }
    __syncthreads();

    if (s_last) {                          // block-uniform branch
        __shared__ int ws2[8];
        int t = threadIdx.x;
        int bv = 0, bi = 0;
        if (t < SCAN_BLOCKS) {
            bv = g_blocksums[t];
            bi = bv;
            #pragma unroll
            for (int d = 1; d < 32; d <<= 1) {
                int u = __shfl_up_sync(0xffffffffu, bi, d);
                if ((t & 31) >= d) bi += u;
            }
            if ((t & 31) == 31) ws2[t >> 5] = bi;
        }
        __syncthreads();
        if (t < SCAN_BLOCKS) {
            int add = 0;
            #pragma unroll
            for (int wq = 0; wq < 8; wq++)
                if (wq < (t >> 5)) add += ws2[wq];
            g_prefix[t] = bi - bv + add;   // exclusive base for block t
        }
        __syncthreads();
        if (t == 0) {
            __threadfence();
            atomicExch(&g_flag, 1);        // publish
        }
    }

    if (threadIdx.x == 0) {                // single-hop wait
        while (atomicAdd(&g_flag, 0) == 0) { __nanosleep(100); }
        __threadfence();
        s_base = g_prefix[bid];
    }
    __syncthreads();

    g_offsets[i] = incl - v + wexcl[wid] + s_base;
    if (bid == SCAN_BLOCKS - 1 && threadIdx.x == 1023)
        g_offsets[SEGS] = n;               // sentinel for count derivation
}

// atomic-free scatter: position = offsets[idx] + rank (offsets L2-hot, 1MB)
__global__ void k_scatter(int n) {
    int i = blockIdx.x * blockDim.x + threadIdx.x;
    if (i >= n) return;
    int packed = g_idx[i];
    int idx  = packed & (SEGS - 1);
    int rank = ((unsigned)packed) >> IDX_BITS;
    g_pids[g_offsets[idx] + rank] = i;
}

// Gather: block = 32 contiguous cells; pids staged in smem (contiguous range).
// Warp handles 4 cells via half-warp partitioning: lanes 0-15 own cells
// (c0,c0+1), lanes 16-31 own (c0+2,c0+3). Each lane holds one float4 column;
// 16 lanes = one full 256B row. Per iteration the warp issues 2 LDG.128
// covering 4 independent rows — concurrency WITHOUT extra accumulator regs.
// No cross-lane combine: each half-warp stores its own rows.
__global__ void __launch_bounds__(256, 6)
k_gather(const float4* __restrict__ x4, float4* __restrict__ out4) {
    if (blockIdx.x == 0 && threadIdx.x == 0) { g_done = 0; g_flag = 0; }

    __shared__ int s_off[CPB + 1];
    __shared__ int s_pid[STAGE_MAX];

    int tid   = threadIdx.x;
    int cbase = blockIdx.x * CPB;

    if (tid < CPB + 1)
        s_off[tid] = g_offsets[cbase + tid];
    __syncthreads();

    int base0 = s_off[0];
    int total = s_off[CPB] - base0;
    bool all_staged = (total <= STAGE_MAX);
    int stage = all_staged ? total : 0;
    for (int i = tid; i < stage; i += 256)
        s_pid[i] = g_pids[base0 + i];
    __syncthreads();

    int warp = tid >> 5;
    int lane = tid & 31;
    int g    = lane >> 4;        // half-warp id (0/1)
    int s    = lane & 15;        // float4 column within 64-ch row
    int cA   = warp * 4 + g * 2; // this half-warp's first cell
    int cB   = cA + 1;           // second cell

    int offA = s_off[cA],  offB = s_off[cB];
    int cntA = s_off[cA + 1] - offA;
    int cntB = s_off[cB + 1] - offB;
    int lsA  = offA - base0,  lsB = offB - base0;

    // warp-wide max iteration count (loop is lockstep; loads predicated)
    int jmax = cntA > cntB ? cntA : cntB;
    #pragma unroll
    for (int d = 16; d; d >>= 1) {
        int u = __shfl_xor_sync(0xffffffffu, jmax, d);
        jmax = u > jmax ? u : jmax;
    }

    const float ninf = __int_as_float(0xff800000);
    float4 accA = make_float4(ninf, ninf, ninf, ninf);
    float4 accB = make_float4(ninf, ninf, ninf, ninf);

    for (int j = 0; j < jmax; j++) {
        if (j < cntA) {
            int pid = all_staged ? s_pid[lsA + j] : g_pids[base0 + lsA + j];
            float4 v = x4[pid * 16 + s];
            accA.x = fmaxf(accA.x, v.x);
            accA.y = fmaxf(accA.y, v.y);
            accA.z = fmaxf(accA.z, v.z);
            accA.w = fmaxf(accA.w, v.w);
        }
        if (j < cntB) {
            int pid = all_staged ? s_pid[lsB + j] : g_pids[base0 + lsB + j];
            float4 v = x4[pid * 16 + s];
            accB.x = fmaxf(accB.x, v.x);
            accB.y = fmaxf(accB.y, v.y);
            accB.z = fmaxf(accB.z, v.z);
            accB.w = fmaxf(accB.w, v.w);
        }
    }

    if (cntA == 0) accA = make_float4(0.f, 0.f, 0.f, 0.f);
    if (cntB == 0) accB = make_float4(0.f, 0.f, 0.f, 0.f);
    out4[(cbase + cA) * 16 + s] = accA;   // 16 lanes -> full 256B row
    out4[(cbase + cB) * 16 + s] = accB;
}

// ---------------------------------------------------------------
extern "C" void kernel_launch(void* const* d_in, const int* in_sizes, int n_in,
                              void* d_out, int out_size) {
    const float* x     = (const float*)d_in[0];
    const int2*  pos   = (const int2*)d_in[1];
    const int*   batch = (const int*)d_in[2];
    float* out = (float*)d_out;
    int n = in_sizes[2];     // number of points

    k_hist   <<<(n + 255) / 256, 256>>>(pos, batch, n);
    k_scan   <<<SCAN_BLOCKS, 1024>>>(n);
    k_scatter<<<(n + 255) / 256, 256>>>(n);
    k_gather <<<SEGS / CPB, 256>>>((const float4*)x, (float4*)out);
}

// round 9
// speedup vs baseline: 1.1492x; 1.0040x over previous
#include <cuda_runtime.h>

#define N_MAX     1048576
#define SEGS      (64 * 4096)   // 262144 segments
#define GRID_DIM  64
#define NUM_CELLS 4096
#define PREP_BLOCKS 256
#define CPB       32            // cells per gather block
#define STAGE_MAX 512           // staged pids per gather block
#define IDX_BITS  18            // SEGS = 2^18

// ---- scratch (static device globals; zero-initialized at module load) ----
__device__ int g_idx[N_MAX];           // packed: cell idx | rank<<18
__device__ int g_pids[N_MAX];          // point ids sorted by cell
__device__ int g_counts[SEGS];         // points per cell (re-zeroed in scan phase)
__device__ int g_offsets[SEGS + 1];    // exclusive prefix + sentinel
__device__ int g_blocksums[PREP_BLOCKS];
__device__ int g_prefix[PREP_BLOCKS];  // exclusive scan of block totals
// sync state (all reset by k_gather block 0 for the next graph replay)
__device__ int g_d1, g_f1;             // hist -> scan
__device__ int g_d2, g_f2;             // scan publish
__device__ int g_d3, g_f3;             // scan -> scatter

// single-hop grid barrier: all blocks must be co-resident.
__device__ __forceinline__ void grid_sync(int* done, int* flag) {
    __syncthreads();
    if (threadIdx.x == 0) {
        __threadfence();
        int t = atomicAdd(done, 1);
        if (t == PREP_BLOCKS - 1) {
            atomicExch(flag, 1);
        } else {
            while (atomicAdd(flag, 0) == 0) { __nanosleep(64); }
        }
        __threadfence();
    }
    __syncthreads();
}

// ---------------------------------------------------------------
// Fused hist -> scan -> scatter. 256 blocks x 1024 threads, all co-resident
// (2048 thr/SM on sm_103a). Intermediates (g_idx, counts, offsets) stay in L2
// across phases; two kernel launches are eliminated.
// pos/batch are int32 (JAX x64 disabled => int64 request materializes int32).
__global__ void __launch_bounds__(1024) k_prep(const int2* __restrict__ pos,
                                               const int* __restrict__ batch,
                                               int n) {
    int gtid = blockIdx.x * 1024 + threadIdx.x;   // 0..262143

    // ---- Phase A: histogram + packed idx|rank ----
    #pragma unroll
    for (int k = 0; k < 4; k++) {
        int i = gtid + k * (PREP_BLOCKS * 1024);
        if (i < n) {
            int2 p = pos[i];
            int idx = batch[i] * NUM_CELLS
                    + (p.x >> 2) * GRID_DIM
                    + (p.y >> 2);
            int rank = atomicAdd(&g_counts[idx], 1);
            g_idx[i] = idx | (rank << IDX_BITS);
        }
    }
    grid_sync(&g_d1, &g_f1);

    // ---- Phase B: exclusive scan of counts (single-hop publish) ----
    {
        int bid  = blockIdx.x;
        int i    = gtid;
        int lane = threadIdx.x & 31;
        int wid  = threadIdx.x >> 5;

        int v = g_counts[i];
        g_counts[i] = 0;                       // reset for next replay

        int incl = v;
        #pragma unroll
        for (int d = 1; d < 32; d <<= 1) {
            int u = __shfl_up_sync(0xffffffffu, incl, d);
            if (lane >= d) incl += u;
        }
        __shared__ int ws[32];
        __shared__ int wexcl[32];
        __shared__ int s_last;
        __shared__ int s_base;
        if (lane == 31) ws[wid] = incl;
        __syncthreads();
        if (wid == 0) {
            int w  = ws[lane];
            int wi = w;
            #pragma unroll
            for (int d = 1; d < 32; d <<= 1) {
                int u = __shfl_up_sync(0xffffffffu, wi, d);
                if (lane >= d) wi += u;
            }
            wexcl[lane] = wi - w;
            if (lane == 31) {
                g_blocksums[bid] = wi;         // block total
                __threadfence();
                int t = atomicAdd(&g_d2, 1);
                s_last = (t == PREP_BLOCKS - 1);
            }
        }
        __syncthreads();

        if (s_last) {                          // block-uniform branch
            __shared__ int ws2[8];
            int t = threadIdx.x;
            int bv = 0, bi = 0;
            if (t < PREP_BLOCKS) {
                bv = g_blocksums[t];
                bi = bv;
                #pragma unroll
                for (int d = 1; d < 32; d <<= 1) {
                    int u = __shfl_up_sync(0xffffffffu, bi, d);
                    if ((t & 31) >= d) bi += u;
                }
                if ((t & 31) == 31) ws2[t >> 5] = bi;
            }
            __syncthreads();
            if (t < PREP_BLOCKS) {
                int add = 0;
                #pragma unroll
                for (int wq = 0; wq < 8; wq++)
                    if (wq < (t >> 5)) add += ws2[wq];
                g_prefix[t] = bi - bv + add;   // exclusive base for block t
            }
            __syncthreads();
            if (t == 0) {
                __threadfence();
                atomicExch(&g_f2, 1);          // publish
            }
        }

        if (threadIdx.x == 0) {                // single-hop wait
            while (atomicAdd(&g_f2, 0) == 0) { __nanosleep(64); }
            __threadfence();
            s_base = g_prefix[bid];
        }
        __syncthreads();

        g_offsets[i] = incl - v + wexcl[wid] + s_base;
        if (bid == PREP_BLOCKS - 1 && threadIdx.x == 1023)
            g_offsets[SEGS] = n;               // sentinel
    }
    grid_sync(&g_d3, &g_f3);                   // all offsets visible

    // ---- Phase C: atomic-free scatter ----
    #pragma unroll
    for (int k = 0; k < 4; k++) {
        int i = gtid + k * (PREP_BLOCKS * 1024);
        if (i < n) {
            int packed = g_idx[i];
            int idx  = packed & (SEGS - 1);
            int rank = ((unsigned)packed) >> IDX_BITS;
            g_pids[g_offsets[idx] + rank] = i;
        }
    }
}

// Gather (unchanged from R8 winner): block = 32 contiguous cells; pids staged
// in smem. Half-warp partitioning: lanes 0-15 own cells (c0,c0+1), lanes
// 16-31 own (c0+2,c0+3); each lane = one float4 column, 16 lanes = full 256B
// row. 4 independent rows in flight per warp iteration at zero extra regs.
__global__ void __launch_bounds__(256, 6)
k_gather(const float4* __restrict__ x4, float4* __restrict__ out4) {
    if (blockIdx.x == 0 && threadIdx.x == 0) {
        g_d1 = 0; g_f1 = 0; g_d2 = 0; g_f2 = 0; g_d3 = 0; g_f3 = 0;
    }

    __shared__ int s_off[CPB + 1];
    __shared__ int s_pid[STAGE_MAX];

    int tid   = threadIdx.x;
    int cbase = blockIdx.x * CPB;

    if (tid < CPB + 1)
        s_off[tid] = g_offsets[cbase + tid];
    __syncthreads();

    int base0 = s_off[0];
    int total = s_off[CPB] - base0;
    bool all_staged = (total <= STAGE_MAX);
    int stage = all_staged ? total : 0;
    for (int i = tid; i < stage; i += 256)
        s_pid[i] = g_pids[base0 + i];
    __syncthreads();

    int warp = tid >> 5;
    int lane = tid & 31;
    int g    = lane >> 4;        // half-warp id (0/1)
    int s    = lane & 15;        // float4 column within 64-ch row
    int cA   = warp * 4 + g * 2; // this half-warp's first cell
    int cB   = cA + 1;           // second cell

    int offA = s_off[cA],  offB = s_off[cB];
    int cntA = s_off[cA + 1] - offA;
    int cntB = s_off[cB + 1] - offB;
    int lsA  = offA - base0,  lsB = offB - base0;

    int jmax = cntA > cntB ? cntA : cntB;
    #pragma unroll
    for (int d = 16; d; d >>= 1) {
        int u = __shfl_xor_sync(0xffffffffu, jmax, d);
        jmax = u > jmax ? u : jmax;
    }

    const float ninf = __int_as_float(0xff800000);
    float4 accA = make_float4(ninf, ninf, ninf, ninf);
    float4 accB = make_float4(ninf, ninf, ninf, ninf);

    for (int j = 0; j < jmax; j++) {
        if (j < cntA) {
            int pid = all_staged ? s_pid[lsA + j] : g_pids[base0 + lsA + j];
            float4 v = x4[pid * 16 + s];
            accA.x = fmaxf(accA.x, v.x);
            accA.y = fmaxf(accA.y, v.y);
            accA.z = fmaxf(accA.z, v.z);
            accA.w = fmaxf(accA.w, v.w);
        }
        if (j < cntB) {
            int pid = all_staged ? s_pid[lsB + j] : g_pids[base0 + lsB + j];
            float4 v = x4[pid * 16 + s];
            accB.x = fmaxf(accB.x, v.x);
            accB.y = fmaxf(accB.y, v.y);
            accB.z = fmaxf(accB.z, v.z);
            accB.w = fmaxf(accB.w, v.w);
        }
    }

    if (cntA == 0) accA = make_float4(0.f, 0.f, 0.f, 0.f);
    if (cntB == 0) accB = make_float4(0.f, 0.f, 0.f, 0.f);
    out4[(cbase + cA) * 16 + s] = accA;   // 16 lanes -> full 256B row
    out4[(cbase + cB) * 16 + s] = accB;
}

// ---------------------------------------------------------------
extern "C" void kernel_launch(void* const* d_in, const int* in_sizes, int n_in,
                              void* d_out, int out_size) {
    const float* x     = (const float*)d_in[0];
    const int2*  pos   = (const int2*)d_in[1];
    const int*   batch = (const int*)d_in[2];
    float* out = (float*)d_out;
    int n = in_sizes[2];     // number of points

    k_prep  <<<PREP_BLOCKS, 1024>>>(pos, batch, n);
    k_gather<<<SEGS / CPB, 256>>>((const float4*)x, (float4*)out);
}